// round 16
// baseline (speedup 1.0000x reference)
#include <cuda_runtime.h>
#include <cuda_bf16.h>
#include <cstdint>
#include <cstdio>

#define B_  128
#define S_  50
#define T_  32
#define TQ_ 32
#define H_  256
#define V_  50257
#define G3  768
#define KTOT 768
#define VPAD 50304

typedef unsigned long long ull;
typedef __nv_bfloat16 bf16;

// ---------------- scratch (device globals; no allocation) ----------------
__device__ bf16  g_ctxA[B_*S_*KTOT];
__device__ bf16  g_qA  [B_*TQ_*KTOT];
__device__ bf16  g_afA [B_*KTOT];
__device__ bf16  g_wfA [G3*KTOT];
__device__ bf16  g_wbA [G3*KTOT];
__device__ bf16  g_wqA [G3*KTOT];
__device__ float g_gif [B_*S_*G3];
__device__ float g_gib [B_*S_*G3];
__device__ float g_giq [B_*TQ_*G3];
__device__ float g_outf[B_*S_*H_];
__device__ float g_outb[B_*S_*H_];
__device__ float g_q   [B_*H_];

// ---------------- helpers ----------------
__device__ __forceinline__ float fexp_(float x){
    float y;
    asm("ex2.approx.ftz.f32 %0, %1;" : "=f"(y) : "f"(x * 1.4426950408889634f));
    return y;
}
__device__ __forceinline__ float frcp_(float x){
    float y; asm("rcp.approx.ftz.f32 %0, %1;" : "=f"(y) : "f"(x)); return y;
}
__device__ __forceinline__ float fsig_(float x){ return frcp_(1.f + fexp_(-x)); }
__device__ __forceinline__ float ftanh_(float x){ return 2.f*frcp_(1.f + fexp_(-2.f*x)) - 1.f; }

__device__ __forceinline__ void split_bf16_(float v, bf16& hi, bf16& lo){
    hi = __float2bfloat16(v);
    lo = __float2bfloat16(v - __bfloat162float(hi));
}
__device__ __forceinline__ unsigned pack_bf2_(bf16 a, bf16 b){
    unsigned short x = *reinterpret_cast<unsigned short*>(&a);
    unsigned short y = *reinterpret_cast<unsigned short*>(&b);
    return (unsigned)x | ((unsigned)y << 16);
}
__device__ __forceinline__ unsigned smem_u32_(const void* p){
    unsigned r;
    asm("{ .reg .u64 t; cvta.to.shared.u64 t, %1; cvt.u32.u64 %0, t; }" : "=r"(r) : "l"(p));
    return r;
}
__device__ __forceinline__ unsigned mapa_(unsigned laddr, unsigned rank){
    unsigned r;
    asm("mapa.shared::cluster.u32 %0, %1, %2;" : "=r"(r) : "r"(laddr), "r"(rank));
    return r;
}
__device__ __forceinline__ void st_cluster_u32_(unsigned addr, unsigned v){
    asm volatile("st.shared::cluster.u32 [%0], %1;" :: "r"(addr), "r"(v) : "memory");
}
__device__ __forceinline__ void cluster_arrive_(){
    asm volatile("barrier.cluster.arrive.aligned;" ::: "memory");
}
__device__ __forceinline__ void cluster_wait_(){
    asm volatile("barrier.cluster.wait.aligned;" ::: "memory");
}
__device__ __forceinline__ unsigned ctarank_(){
    unsigned r; asm("mov.u32 %0, %%cluster_ctarank;" : "=r"(r)); return r;
}
__device__ __forceinline__ void mbar_init_(unsigned addr, unsigned cnt){
    asm volatile("mbarrier.init.shared.b64 [%0], %1;" :: "r"(addr), "r"(cnt) : "memory");
}
// arrive with release semantics at cluster scope: orders this thread's prior
// DSMEM stores before the arrival (no standalone fence needed)
__device__ __forceinline__ void mbar_arrive_rel_(unsigned remote_addr){
    asm volatile("mbarrier.arrive.release.cluster.shared::cluster.b64 _, [%0];"
                 :: "r"(remote_addr) : "memory");
}
// wait with acquire semantics at cluster scope: orders subsequent reads after
// all released arrivals (no standalone fence needed)
__device__ __forceinline__ void mbar_wait_parity_acq_(unsigned addr, unsigned parity){
    asm volatile(
        "{\n\t"
        ".reg .pred P1;\n\t"
        "WAIT_LOOP_%=:\n\t"
        "mbarrier.try_wait.parity.acquire.cluster.shared::cta.b64 P1, [%0], %1, 0x989680;\n\t"
        "@P1 bra.uni WAIT_DONE_%=;\n\t"
        "bra.uni WAIT_LOOP_%=;\n\t"
        "WAIT_DONE_%=:\n\t"
        "}"
        :: "r"(addr), "r"(parity) : "memory");
}
__device__ __forceinline__ void mma_bf16_(float4& d, const unsigned a[4], const unsigned b[2]){
    asm("mma.sync.aligned.m16n8k16.row.col.f32.bf16.bf16.f32 "
        "{%0,%1,%2,%3}, {%4,%5,%6,%7}, {%8,%9}, {%0,%1,%2,%3};"
        : "+f"(d.x), "+f"(d.y), "+f"(d.z), "+f"(d.w)
        : "r"(a[0]), "r"(a[1]), "r"(a[2]), "r"(a[3]), "r"(b[0]), "r"(b[1]));
}
__device__ __forceinline__ void ldsm_x4_(unsigned af[4], unsigned addr){
    asm volatile("ldmatrix.sync.aligned.m8n8.x4.shared.b16 {%0,%1,%2,%3}, [%4];"
        : "=r"(af[0]), "=r"(af[1]), "=r"(af[2]), "=r"(af[3]) : "r"(addr));
}

// ---------------- 1) fused prep: embed_pe | qemb | convW3 ----------------
#define PREP_EMB   (B_*S_)                 // 6400
#define PREP_QEMB  (PREP_EMB + B_*TQ_)     // +4096
#define PREP_TOTAL (PREP_QEMB + 3*G3)      // +2304 = 12800

__global__ __launch_bounds__(256) void prep_kernel(
    const int* __restrict__ ctx, const int* __restrict__ q, const float* __restrict__ emb,
    const float* __restrict__ Wf, const float* __restrict__ Wb, const float* __restrict__ Wq)
{
    int bid = blockIdx.x;
    int h   = threadIdx.x;
    if (bid < PREP_EMB){
        int bs = bid;
        __shared__ int ids[T_];
        if (h < T_) ids[h] = ctx[bs*T_ + h];
        __syncthreads();
        float e = (float)h * (1.0f/255.0f);
        float acc = 0.f;
#pragma unroll
        for (int t = 0; t < T_; t++){
            float s = (float)t * (1.0f/31.0f);
            float l = 1.0f - s - e*(1.0f - 2.0f*s);
            acc += emb[(size_t)ids[t]*H_ + h] * l;
        }
        bf16 hi, lo; split_bf16_(acc, hi, lo);
        bf16* dst = g_ctxA + (size_t)bs*KTOT;
        dst[h] = hi; dst[h + 256] = hi; dst[h + 512] = lo;
    } else if (bid < PREP_QEMB){
        int i = bid - PREP_EMB;
        float v = emb[(size_t)q[i]*H_ + h];
        bf16 hi, lo; split_bf16_(v, hi, lo);
        bf16* dst = g_qA + (size_t)i*KTOT;
        dst[h] = hi; dst[h + 256] = hi; dst[h + 512] = lo;
    } else {
        int idx = bid - PREP_QEMB;
        int sel = idx / G3, n = idx % G3;
        const float* W; bf16* D;
        if (sel == 0){ W = Wf; D = g_wfA; }
        else if (sel == 1){ W = Wb; D = g_wbA; }
        else { W = Wq; D = g_wqA; }
        float v = W[(size_t)n*256 + h];
        bf16 hi, lo; split_bf16_(v, hi, lo);
        bf16* dst = D + (size_t)n*KTOT;
        dst[h] = hi; dst[h + 256] = lo; dst[h + 512] = hi;
    }
}

// ---------------- 2) split-bf16 tensor GEMM for gi (tile 128m x 128n) ----------------
#define AST 72
#define BG3_SMEM_BYTES (2*128*AST*2)
__global__ __launch_bounds__(256) void bgemm3_kernel(
    const float* bias_f, const float* bias_b, const float* bias_q)
{
    extern __shared__ bf16 g3s[];
    bf16* As = g3s;             // [128][72]
    bf16* Bs = g3s + 128*AST;   // [128][72]

    const bf16 *A, *W; const float* bias; float* C; int M;
    if (blockIdx.z == 0){ A = g_ctxA; W = g_wfA; bias = bias_f; C = g_gif; M = B_*S_; }
    else if (blockIdx.z == 1){ A = g_ctxA; W = g_wbA; bias = bias_b; C = g_gib; M = B_*S_; }
    else { A = g_qA; W = g_wqA; bias = bias_q; C = g_giq; M = B_*TQ_; }
    int bm = blockIdx.x * 128;
    if (bm >= M) return;
    int bn = blockIdx.y * 128;

    int tid = threadIdx.x;
    int lane = tid & 31, wid = tid >> 5;
    int wm = (wid & 3) * 32;     // 4 m-groups of 32
    int wn = (wid >> 2) * 64;    // 2 n-groups of 64

    float4 acc[2][8];
#pragma unroll
    for (int i = 0; i < 2; i++)
#pragma unroll
        for (int j = 0; j < 8; j++) acc[i][j] = make_float4(0.f,0.f,0.f,0.f);

    for (int k0 = 0; k0 < KTOT; k0 += 64){
#pragma unroll
        for (int i = 0; i < 4; i++){
            int idx = tid + i*256;
            int r = idx >> 3, ck = idx & 7;
            *(uint4*)(As + r*AST + ck*8) = *(const uint4*)(A + (size_t)(bm + r)*KTOT + k0 + ck*8);
            *(uint4*)(Bs + r*AST + ck*8) = *(const uint4*)(W + (size_t)(bn + r)*KTOT + k0 + ck*8);
        }
        __syncthreads();
        int r = lane >> 2, c2 = (lane & 3) * 2;
#pragma unroll
        for (int kk = 0; kk < 4; kk++){
            unsigned af[2][4], bfr[8][2];
#pragma unroll
            for (int i = 0; i < 2; i++){
                const bf16* ab = As + (wm + i*16)*AST + kk*16;
                af[i][0] = *(const unsigned*)(ab + (r    )*AST + c2    );
                af[i][1] = *(const unsigned*)(ab + (r + 8)*AST + c2    );
                af[i][2] = *(const unsigned*)(ab + (r    )*AST + c2 + 8);
                af[i][3] = *(const unsigned*)(ab + (r + 8)*AST + c2 + 8);
            }
#pragma unroll
            for (int j = 0; j < 8; j++){
                const bf16* bb = Bs + (wn + j*8)*AST + kk*16;
                bfr[j][0] = *(const unsigned*)(bb + r*AST + c2    );
                bfr[j][1] = *(const unsigned*)(bb + r*AST + c2 + 8);
            }
#pragma unroll
            for (int i = 0; i < 2; i++)
#pragma unroll
                for (int j = 0; j < 8; j++)
                    mma_bf16_(acc[i][j], af[i], bfr[j]);
        }
        __syncthreads();
    }
    int r = lane >> 2, c2 = (lane & 3) * 2;
#pragma unroll
    for (int i = 0; i < 2; i++){
        int m0 = bm + wm + i*16 + r;
#pragma unroll
        for (int j = 0; j < 8; j++){
            int n0 = bn + wn + j*8 + c2;
            float4 a = acc[i][j];
            float b0 = bias[n0], b1 = bias[n0+1];
            *(float2*)(C + (size_t)m0*G3 + n0)     = make_float2(a.x + b0, a.y + b1);
            *(float2*)(C + (size_t)(m0+8)*G3 + n0) = make_float2(a.z + b0, a.w + b1);
        }
    }
}

// ---------------- 2b) vocab GEMM: inline fp32 W split ----------------
#define VOC_SMEM_BF16 (2*128*AST + 2*64*AST)
#define VOC_SMEM_BYTES (VOC_SMEM_BF16*2)
__global__ __launch_bounds__(256) void bgemm_vocab_kernel(
    const float* __restrict__ Wo, const float* __restrict__ bo, float* __restrict__ out)
{
    extern __shared__ bf16 vs[];
    bf16* Ah = vs;                 // [128][72]
    bf16* Al = vs + 128*AST;       // [128][72]
    bf16* Bh = vs + 2*128*AST;     // [64][72]
    bf16* Bl = Bh + 64*AST;        // [64][72]
    int tid = threadIdx.x;
    int lane = tid & 31, wid = tid >> 5;
    int wm = (wid & 3) * 32;
    int wn = (wid >> 2) * 32;
    int bn = blockIdx.y * 64;

    float4 acc[2][4];
#pragma unroll
    for (int i = 0; i < 2; i++)
#pragma unroll
        for (int j = 0; j < 4; j++) acc[i][j] = make_float4(0.f,0.f,0.f,0.f);

    for (int k0 = 0; k0 < 256; k0 += 64){
#pragma unroll
        for (int i = 0; i < 4; i++){
            int idx = tid + i*256;
            int r = idx >> 3, ck = idx & 7;
            *(uint4*)(Ah + r*AST + ck*8) = *(const uint4*)(g_afA + (size_t)r*KTOT + k0 + ck*8);
            *(uint4*)(Al + r*AST + ck*8) = *(const uint4*)(g_afA + (size_t)r*KTOT + 512 + k0 + ck*8);
        }
#pragma unroll
        for (int i = 0; i < 4; i++){
            int idx = tid + i*256;
            int r = idx >> 4, ck = idx & 15;
            int n = bn + r;
            float4 v = make_float4(0.f,0.f,0.f,0.f);
            if (n < V_) v = *(const float4*)(Wo + (size_t)n*256 + k0 + ck*4);
            bf16 h0,l0,h1,l1,h2,l2,h3,l3;
            split_bf16_(v.x,h0,l0); split_bf16_(v.y,h1,l1);
            split_bf16_(v.z,h2,l2); split_bf16_(v.w,h3,l3);
            *(uint2*)(Bh + r*AST + ck*4) = make_uint2(pack_bf2_(h0,h1), pack_bf2_(h2,h3));
            *(uint2*)(Bl + r*AST + ck*4) = make_uint2(pack_bf2_(l0,l1), pack_bf2_(l2,l3));
        }
        __syncthreads();
        int r = lane >> 2, c2 = (lane & 3) * 2;
#pragma unroll
        for (int kk = 0; kk < 4; kk++){
            unsigned ah[2][4], al[2][4], bh[4][2], bl[4][2];
#pragma unroll
            for (int i = 0; i < 2; i++){
                const bf16* ab = Ah + (wm + i*16)*AST + kk*16;
                const bf16* al_ = Al + (wm + i*16)*AST + kk*16;
                ah[i][0] = *(const unsigned*)(ab  + (r    )*AST + c2    );
                ah[i][1] = *(const unsigned*)(ab  + (r + 8)*AST + c2    );
                ah[i][2] = *(const unsigned*)(ab  + (r    )*AST + c2 + 8);
                ah[i][3] = *(const unsigned*)(ab  + (r + 8)*AST + c2 + 8);
                al[i][0] = *(const unsigned*)(al_ + (r    )*AST + c2    );
                al[i][1] = *(const unsigned*)(al_ + (r + 8)*AST + c2    );
                al[i][2] = *(const unsigned*)(al_ + (r    )*AST + c2 + 8);
                al[i][3] = *(const unsigned*)(al_ + (r + 8)*AST + c2 + 8);
            }
#pragma unroll
            for (int j = 0; j < 4; j++){
                const bf16* bbh = Bh + (wn + j*8)*AST + kk*16;
                const bf16* bbl = Bl + (wn + j*8)*AST + kk*16;
                bh[j][0] = *(const unsigned*)(bbh + r*AST + c2    );
                bh[j][1] = *(const unsigned*)(bbh + r*AST + c2 + 8);
                bl[j][0] = *(const unsigned*)(bbl + r*AST + c2    );
                bl[j][1] = *(const unsigned*)(bbl + r*AST + c2 + 8);
            }
#pragma unroll
            for (int i = 0; i < 2; i++)
#pragma unroll
                for (int j = 0; j < 4; j++){
                    mma_bf16_(acc[i][j], ah[i], bh[j]);
                    mma_bf16_(acc[i][j], ah[i], bl[j]);
                    mma_bf16_(acc[i][j], al[i], bh[j]);
                }
        }
        __syncthreads();
    }
    int r = lane >> 2, c2 = (lane & 3) * 2;
#pragma unroll
    for (int i = 0; i < 2; i++){
        int m0 = wm + i*16 + r;
#pragma unroll
        for (int j = 0; j < 4; j++){
            int n0 = bn + wn + j*8 + c2;
            if (n0 < V_){
                float4 a = acc[i][j];
                float b0 = bo[n0];
                out[(size_t)m0*V_ + n0]     = a.x + b0;
                out[(size_t)(m0+8)*V_ + n0] = a.z + b0;
                if (n0 + 1 < V_){
                    float b1 = bo[n0+1];
                    out[(size_t)m0*V_ + n0 + 1]     = a.y + b1;
                    out[(size_t)(m0+8)*V_ + n0 + 1] = a.w + b1;
                }
            }
        }
    }
}

// ---------------- 3) GRU on tensor cores (R13 structure; fused release/acquire) ----
#define GRU_WST 264
#define GRU_HST 520
#define GRU_WPLANE (192*GRU_WST)
#define GRU_SMEM_BF16 (2*GRU_WPLANE + 16*GRU_HST)
#define GRU_SMEM_BYTES (GRU_SMEM_BF16*2)

__global__ void __cluster_dims__(4,1,1) __launch_bounds__(256,1)
gru_kernel(const float* __restrict__ Whh_f, const float* __restrict__ Whh_b, const float* __restrict__ Whh_q,
           const float* __restrict__ bhh_f, const float* __restrict__ bhh_b, const float* __restrict__ bhh_q)
{
    extern __shared__ bf16 smb[];
    __shared__ ull gru_mbar;              // static smem mbarrier (never aliased)
    bf16* Whi   = smb;                    // [192][264] (dead after preload)
    bf16* Wlo   = smb + GRU_WPLANE;       // [192][264]
    bf16* hbuf0 = smb + 2*GRU_WPLANE;     // [16][520]: k 0-255 hi, 256-511 lo
    bf16* hbuf1 = smb;                    // aliases Whi region

    int tid  = threadIdx.x;
    int lane = tid & 31, w = tid >> 5;
    unsigned rank = ctarank_();
    int cid   = blockIdx.x >> 2;
    int chain = cid >> 3;
    int b0    = (cid & 7) * 16;

    const float *Whh, *bhh, *gi;
    float* outp;
    int steps;
    if (chain == 0){ Whh = Whh_f; bhh = bhh_f; gi = g_gif; outp = g_outf; steps = S_;  }
    else if (chain == 1){ Whh = Whh_b; bhh = bhh_b; gi = g_gib; outp = g_outb; steps = S_;  }
    else { Whh = Whh_q; bhh = bhh_q; gi = g_giq; outp = g_q;    steps = TQ_; }

    unsigned mbar_addr = smem_u32_(&gru_mbar);
    if (tid == 0) mbar_init_(mbar_addr, 1024u);

    // ---- stage + split Whh slice into smem; zero hbuf0
    {
#pragma unroll 4
        for (int rr = 0; rr < 192; rr++){
            int grow = (rr >> 6)*256 + (int)rank*64 + (rr & 63);
            float v = Whh[(size_t)grow*256 + tid];
            bf16 hi, lo; split_bf16_(v, hi, lo);
            Whi[rr*GRU_WST + tid] = hi;
            Wlo[rr*GRU_WST + tid] = lo;
        }
        unsigned* hz = (unsigned*)hbuf0;
        for (int i = tid; i < 16*GRU_HST/2; i += 256) hz[i] = 0u;
    }
    __syncthreads();

    // ---- fragment geometry
    int r  = lane >> 2;
    int c2 = (lane & 3) * 2;
    int jglob0 = (int)rank*64 + w*8 + c2;

    // ---- preload W fragments to registers: Bf[kt][gate][plane][reg]
    unsigned Bf[16][3][2][2];
#pragma unroll
    for (int kt = 0; kt < 16; kt++){
#pragma unroll
        for (int g = 0; g < 3; g++){
            const bf16* ph = Whi + (g*64 + w*8 + r)*GRU_WST + kt*16 + c2;
            const bf16* pl = Wlo + (g*64 + w*8 + r)*GRU_WST + kt*16 + c2;
            Bf[kt][g][0][0] = *(const unsigned*)(ph);
            Bf[kt][g][0][1] = *(const unsigned*)(ph + 8);
            Bf[kt][g][1][0] = *(const unsigned*)(pl);
            Bf[kt][g][1][1] = *(const unsigned*)(pl + 8);
        }
    }

    unsigned hb0 = smem_u32_(hbuf0), hb1 = smem_u32_(hbuf1);
    unsigned arow = (unsigned)((lane & 15)*GRU_HST*2 + ((lane >> 4) << 3)*2);

    // peer mbarrier addresses (fixed; hoisted)
    unsigned mb0 = mapa_(mbar_addr, 0), mb1 = mapa_(mbar_addr, 1);
    unsigned mb2 = mapa_(mbar_addr, 2), mb3 = mapa_(mbar_addr, 3);

    // DSMEM write-target bases for both buffers (hoisted; wb alternates)
    unsigned pw0[4], pw1[4];
#pragma unroll
    for (int i = 0; i < 4; i++){ pw0[i] = mapa_(hb1, (unsigned)i); pw1[i] = mapa_(hb0, (unsigned)i); }

    int bbA = b0 + r, bbB = b0 + r + 8;
    float hpA0 = 0.f, hpA1 = 0.f, hpB0 = 0.f, hpB1 = 0.f;

    // biases are step-invariant: hoist
    float2 br2 = *(const float2*)(bhh       + jglob0);
    float2 bz2 = *(const float2*)(bhh + 256 + jglob0);
    float2 bn2 = *(const float2*)(bhh + 512 + jglob0);

    // staging + preloads + mbarrier init visible cluster-wide before step 0
    cluster_arrive_();
    cluster_wait_();

    for (int step = 0; step < steps; step++){
        int pos = (chain == 1) ? (S_ - 1 - step) : step;
        unsigned rb = (step & 1) ? hb1 : hb0;
        const unsigned* pw = (step & 1) ? pw1 : pw0;
        unsigned abase = rb + arow;
        bool last = (step == steps - 1);

        float4 accR = make_float4(0.f,0.f,0.f,0.f);
        float4 accZ = make_float4(0.f,0.f,0.f,0.f);
        float4 accN = make_float4(0.f,0.f,0.f,0.f);

        // pass 1: A = h_hi, B = W_hi then W_lo (registers)
#pragma unroll
        for (int kt = 0; kt < 16; kt++){
            unsigned af[4];
            ldsm_x4_(af, abase + kt*32);
            mma_bf16_(accR, af, Bf[kt][0][0]);
            mma_bf16_(accZ, af, Bf[kt][1][0]);
            mma_bf16_(accN, af, Bf[kt][2][0]);
            mma_bf16_(accR, af, Bf[kt][0][1]);
            mma_bf16_(accZ, af, Bf[kt][1][1]);
            mma_bf16_(accN, af, Bf[kt][2][1]);
        }

        // gi loads issue here; latency hidden under pass 2
        float2 grA, gzA, gnA, grB, gzB, gnB;
        {
            const float* pA = gi + ((size_t)bbA*steps + pos)*G3 + jglob0;
            const float* pB = gi + ((size_t)bbB*steps + pos)*G3 + jglob0;
            grA = *(const float2*)(pA); gzA = *(const float2*)(pA+256); gnA = *(const float2*)(pA+512);
            grB = *(const float2*)(pB); gzB = *(const float2*)(pB+256); gnB = *(const float2*)(pB+512);
        }

        // pass 2: A = h_lo (k+512B), B = W_hi
#pragma unroll
        for (int kt = 0; kt < 16; kt++){
            unsigned af[4];
            ldsm_x4_(af, abase + 512 + kt*32);
            mma_bf16_(accR, af, Bf[kt][0][0]);
            mma_bf16_(accZ, af, Bf[kt][1][0]);
            mma_bf16_(accN, af, Bf[kt][2][0]);
        }

        float rA0 = fsig_(grA.x + accR.x + br2.x);
        float zA0 = fsig_(gzA.x + accZ.x + bz2.x);
        float nA0 = ftanh_(gnA.x + rA0*(accN.x + bn2.x));
        float hA0 = (1.f - zA0)*nA0 + zA0*hpA0; hpA0 = hA0;
        float rA1 = fsig_(grA.y + accR.y + br2.y);
        float zA1 = fsig_(gzA.y + accZ.y + bz2.y);
        float nA1 = ftanh_(gnA.y + rA1*(accN.y + bn2.y));
        float hA1 = (1.f - zA1)*nA1 + zA1*hpA1; hpA1 = hA1;
        float rB0 = fsig_(grB.x + accR.z + br2.x);
        float zB0 = fsig_(gzB.x + accZ.z + bz2.x);
        float nB0 = ftanh_(gnB.x + rB0*(accN.z + bn2.x));
        float hB0 = (1.f - zB0)*nB0 + zB0*hpB0; hpB0 = hB0;
        float rB1 = fsig_(grB.y + accR.w + br2.y);
        float zB1 = fsig_(gzB.y + accZ.w + bz2.y);
        float nB1 = ftanh_(gnB.y + rB1*(accN.w + bn2.y));
        float hB1 = (1.f - zB1)*nB1 + zB1*hpB1; hpB1 = hB1;

        if (!last){
            bf16 hiA0, loA0, hiA1, loA1, hiB0, loB0, hiB1, loB1;
            split_bf16_(hA0, hiA0, loA0); split_bf16_(hA1, hiA1, loA1);
            split_bf16_(hB0, hiB0, loB0); split_bf16_(hB1, hiB1, loB1);
            unsigned uAhi = pack_bf2_(hiA0, hiA1), uAlo = pack_bf2_(loA0, loA1);
            unsigned uBhi = pack_bf2_(hiB0, hiB1), uBlo = pack_bf2_(loB0, loB1);

            unsigned offAhi = (unsigned)((r*GRU_HST + jglob0)*2);
            unsigned offAlo = offAhi + 512;
            unsigned offBhi = (unsigned)(((r+8)*GRU_HST + jglob0)*2);
            unsigned offBlo = offBhi + 512;
            st_cluster_u32_(pw[0] + offAhi, uAhi); st_cluster_u32_(pw[0] + offAlo, uAlo);
            st_cluster_u32_(pw[0] + offBhi, uBhi); st_cluster_u32_(pw[0] + offBlo, uBlo);
            st_cluster_u32_(pw[1] + offAhi, uAhi); st_cluster_u32_(pw[1] + offAlo, uAlo);
            st_cluster_u32_(pw[1] + offBhi, uBhi); st_cluster_u32_(pw[1] + offBlo, uBlo);
            st_cluster_u32_(pw[2] + offAhi, uAhi); st_cluster_u32_(pw[2] + offAlo, uAlo);
            st_cluster_u32_(pw[2] + offBhi, uBhi); st_cluster_u32_(pw[2] + offBlo, uBlo);
            st_cluster_u32_(pw[3] + offAhi, uAhi); st_cluster_u32_(pw[3] + offAlo, uAlo);
            st_cluster_u32_(pw[3] + offBhi, uBhi); st_cluster_u32_(pw[3] + offBlo, uBlo);

            // release folded into the arrives (orders this thread's DSMEM stores)
            mbar_arrive_rel_(mb0);
            mbar_arrive_rel_(mb1);
            mbar_arrive_rel_(mb2);
            mbar_arrive_rel_(mb3);
        }

        // global outputs overlap the arrive/wait window
        if (chain == 2){
            if (last){
                *(float2*)(outp + (size_t)bbA*H_ + jglob0) = make_float2(hA0, hA1);
                *(float2*)(outp + (size_t)bbB*H_ + jglob0) = make_float2(hB0, hB1);
            }
        } else {
            *(float2*)(outp + ((size_t)bbA*S_ + pos)*H_ + jglob0) = make_float2(hA0, hA1);
            *(float2*)(outp + ((size_t)bbB*S_ + pos)*H_ + jglob0) = make_float2(hB0, hB1);
        }

        if (!last){
            // acquire folded into the wait (orders subsequent reads)
            mbar_wait_parity_acq_(mbar_addr, (unsigned)(step & 1));
        }
    }
}

// ---------------- 4) attention: 512 threads, smem-cached facts ----------------
#define ATT_SMEM_BYTES (S_*H_*4 + 2*S_*4 + H_*4)
__global__ __launch_bounds__(512) void attn_kernel(){
    extern __shared__ float fs[];          // [S_][H_] cached f = outf+outb
    float* en   = fs + S_*H_;
    float* aw   = en + S_;
    float* red2 = aw + S_;                 // [H_] partial sums from half 1
    int b = blockIdx.x, tid = threadIdx.x;
    int lane = tid & 31, w = tid >> 5;     // 16 warps
    const float* pq = g_q + (size_t)b*H_;

    for (int s = w; s < S_; s += 16){
        const float* pf = g_outf + ((size_t)b*S_ + s)*H_;
        const float* pb = g_outb + ((size_t)b*S_ + s)*H_;
        float p = 0.f;
#pragma unroll
        for (int c = 0; c < 8; c++){
            int hh = c*32 + lane;
            float f = pf[hh] + pb[hh];
            fs[s*H_ + hh] = f;
            p += f * pq[hh];
        }
#pragma unroll
        for (int o = 16; o; o >>= 1) p += __shfl_xor_sync(0xffffffffu, p, o);
        if (lane == 0) en[s] = p;
    }
    __syncthreads();

    if (tid < S_){
        float mx = -1e30f;
        for (int s = 0; s < S_; s++) mx = fmaxf(mx, en[s]);
        float sum = 0.f;
        for (int s = 0; s < S_; s++) sum += fexp_(en[s] - mx);
        aw[tid] = fexp_(en[tid] - mx) * frcp_(sum);
    }
    __syncthreads();

    int h = tid & 255, half = tid >> 8;
    float rd = 0.f;
#pragma unroll 5
    for (int s = half; s < S_; s += 2) rd += aw[s] * fs[s*H_ + h];
    if (half) red2[h] = rd;
    __syncthreads();
    if (!half){
        float v = ftanh_(pq[h] * (rd + red2[h]));
        bf16 hi, lo; split_bf16_(v, hi, lo);
        bf16* dst = g_afA + (size_t)b*KTOT;
        dst[h] = hi; dst[h + 256] = hi; dst[h + 512] = lo;
    }
}

// ---------------- launch ----------------
extern "C" void kernel_launch(void* const* d_in, const int* in_sizes, int n_in,
                              void* d_out, int out_size)
{
    const int*   contexts  = (const int*)  d_in[0];
    const int*   questions = (const int*)  d_in[1];
    const float* emb       = (const float*)d_in[2];
    const float* Wih_f     = (const float*)d_in[3];
    const float* Whh_f     = (const float*)d_in[4];
    const float* bih_f     = (const float*)d_in[5];
    const float* bhh_f     = (const float*)d_in[6];
    const float* Wih_b     = (const float*)d_in[7];
    const float* Whh_b     = (const float*)d_in[8];
    const float* bih_b     = (const float*)d_in[9];
    const float* bhh_b     = (const float*)d_in[10];
    const float* Wih_q     = (const float*)d_in[11];
    const float* Whh_q     = (const float*)d_in[12];
    const float* bih_q     = (const float*)d_in[13];
    const float* bhh_q     = (const float*)d_in[14];
    const float* Wo        = (const float*)d_in[15];
    const float* bo        = (const float*)d_in[16];
    float* out = (float*)d_out;

    cudaFuncSetAttribute(gru_kernel, cudaFuncAttributeMaxDynamicSharedMemorySize, GRU_SMEM_BYTES);
    cudaFuncSetAttribute(bgemm_vocab_kernel, cudaFuncAttributeMaxDynamicSharedMemorySize, VOC_SMEM_BYTES);
    cudaFuncSetAttribute(attn_kernel, cudaFuncAttributeMaxDynamicSharedMemorySize, ATT_SMEM_BYTES);
    cudaFuncSetAttribute(bgemm3_kernel, cudaFuncAttributeMaxDynamicSharedMemorySize, BG3_SMEM_BYTES);

    // 1) fused prep: embeddings + gi weight splits in ONE launch
    prep_kernel<<<PREP_TOTAL, 256>>>(contexts, questions, emb, Wih_f, Wih_b, Wih_q);

    // 2) input-gate GEMMs on tensor cores (128x128 tiles)
    bgemm3_kernel<<<dim3(B_*S_/128, G3/128, 3), 256, BG3_SMEM_BYTES>>>(bih_f, bih_b, bih_q);

    // 3) GRU chains on tensor cores (fused release/acquire mbarrier sync)
    gru_kernel<<<96, 256, GRU_SMEM_BYTES>>>(Whh_f, Whh_b, Whh_q, bhh_f, bhh_b, bhh_q);

    // 4) attention + read + tanh (512 threads, smem-cached facts)
    attn_kernel<<<B_, 512, ATT_SMEM_BYTES>>>();

    // 5) vocab projection on tensor cores, inline fp32 W split
    bgemm_vocab_kernel<<<dim3(1, VPAD/64), 256, VOC_SMEM_BYTES>>>(Wo, bo, out);
}

// round 17
// speedup vs baseline: 1.0181x; 1.0181x over previous
#include <cuda_runtime.h>
#include <cuda_bf16.h>
#include <cstdint>
#include <cstdio>

#define B_  128
#define S_  50
#define T_  32
#define TQ_ 32
#define H_  256
#define V_  50257
#define G3  768
#define KTOT 768
#define VPAD 50304

typedef unsigned long long ull;
typedef __nv_bfloat16 bf16;

// ---------------- scratch (device globals; no allocation) ----------------
__device__ bf16  g_ctxA[B_*S_*KTOT];
__device__ bf16  g_qA  [B_*TQ_*KTOT];
__device__ bf16  g_afA [B_*KTOT];
__device__ bf16  g_wfA [G3*KTOT];
__device__ bf16  g_wbA [G3*KTOT];
__device__ bf16  g_wqA [G3*KTOT];
__device__ float g_gif [B_*S_*G3];
__device__ float g_gib [B_*S_*G3];
__device__ float g_giq [B_*TQ_*G3];
__device__ float g_outf[B_*S_*H_];
__device__ float g_outb[B_*S_*H_];
__device__ float g_q   [B_*H_];

// ---------------- helpers ----------------
__device__ __forceinline__ float fexp_(float x){
    float y;
    asm("ex2.approx.ftz.f32 %0, %1;" : "=f"(y) : "f"(x * 1.4426950408889634f));
    return y;
}
__device__ __forceinline__ float frcp_(float x){
    float y; asm("rcp.approx.ftz.f32 %0, %1;" : "=f"(y) : "f"(x)); return y;
}
__device__ __forceinline__ float fsig_(float x){ return frcp_(1.f + fexp_(-x)); }
__device__ __forceinline__ float ftanh_(float x){ return 2.f*frcp_(1.f + fexp_(-2.f*x)) - 1.f; }

__device__ __forceinline__ void split_bf16_(float v, bf16& hi, bf16& lo){
    hi = __float2bfloat16(v);
    lo = __float2bfloat16(v - __bfloat162float(hi));
}
__device__ __forceinline__ unsigned pack_bf2_(bf16 a, bf16 b){
    unsigned short x = *reinterpret_cast<unsigned short*>(&a);
    unsigned short y = *reinterpret_cast<unsigned short*>(&b);
    return (unsigned)x | ((unsigned)y << 16);
}
__device__ __forceinline__ unsigned smem_u32_(const void* p){
    unsigned r;
    asm("{ .reg .u64 t; cvta.to.shared.u64 t, %1; cvt.u32.u64 %0, t; }" : "=r"(r) : "l"(p));
    return r;
}
__device__ __forceinline__ unsigned mapa_(unsigned laddr, unsigned rank){
    unsigned r;
    asm("mapa.shared::cluster.u32 %0, %1, %2;" : "=r"(r) : "r"(laddr), "r"(rank));
    return r;
}
__device__ __forceinline__ void st_cluster_u32_(unsigned addr, unsigned v){
    asm volatile("st.shared::cluster.u32 [%0], %1;" :: "r"(addr), "r"(v) : "memory");
}
__device__ __forceinline__ void cluster_arrive_(){
    asm volatile("barrier.cluster.arrive.aligned;" ::: "memory");
}
__device__ __forceinline__ void cluster_wait_(){
    asm volatile("barrier.cluster.wait.aligned;" ::: "memory");
}
__device__ __forceinline__ unsigned ctarank_(){
    unsigned r; asm("mov.u32 %0, %%cluster_ctarank;" : "=r"(r)); return r;
}
__device__ __forceinline__ void mbar_init_(unsigned addr, unsigned cnt){
    asm volatile("mbarrier.init.shared.b64 [%0], %1;" :: "r"(addr), "r"(cnt) : "memory");
}
__device__ __forceinline__ void mbar_arrive_cluster_(unsigned remote_addr){
    asm volatile("mbarrier.arrive.shared::cluster.b64 _, [%0];" :: "r"(remote_addr) : "memory");
}
__device__ __forceinline__ void mbar_wait_parity_(unsigned addr, unsigned parity){
    asm volatile(
        "{\n\t"
        ".reg .pred P1;\n\t"
        "WAIT_LOOP_%=:\n\t"
        "mbarrier.try_wait.parity.shared::cta.b64 P1, [%0], %1, 0x989680;\n\t"
        "@P1 bra.uni WAIT_DONE_%=;\n\t"
        "bra.uni WAIT_LOOP_%=;\n\t"
        "WAIT_DONE_%=:\n\t"
        "}"
        :: "r"(addr), "r"(parity) : "memory");
}
__device__ __forceinline__ void fence_cluster_(){
    asm volatile("fence.acq_rel.cluster;" ::: "memory");
}
__device__ __forceinline__ void mma_bf16_(float4& d, const unsigned a[4], const unsigned b[2]){
    asm("mma.sync.aligned.m16n8k16.row.col.f32.bf16.bf16.f32 "
        "{%0,%1,%2,%3}, {%4,%5,%6,%7}, {%8,%9}, {%0,%1,%2,%3};"
        : "+f"(d.x), "+f"(d.y), "+f"(d.z), "+f"(d.w)
        : "r"(a[0]), "r"(a[1]), "r"(a[2]), "r"(a[3]), "r"(b[0]), "r"(b[1]));
}
__device__ __forceinline__ void ldsm_x4_(unsigned af[4], unsigned addr){
    asm volatile("ldmatrix.sync.aligned.m8n8.x4.shared.b16 {%0,%1,%2,%3}, [%4];"
        : "=r"(af[0]), "=r"(af[1]), "=r"(af[2]), "=r"(af[3]) : "r"(addr));
}

// ---------------- 1) fused prep: embed_pe | qemb | convW3 ----------------
#define PREP_EMB   (B_*S_)                 // 6400
#define PREP_QEMB  (PREP_EMB + B_*TQ_)     // +4096
#define PREP_TOTAL (PREP_QEMB + 3*G3)      // +2304 = 12800

__global__ __launch_bounds__(256) void prep_kernel(
    const int* __restrict__ ctx, const int* __restrict__ q, const float* __restrict__ emb,
    const float* __restrict__ Wf, const float* __restrict__ Wb, const float* __restrict__ Wq)
{
    int bid = blockIdx.x;
    int h   = threadIdx.x;
    if (bid < PREP_EMB){
        int bs = bid;
        __shared__ int ids[T_];
        if (h < T_) ids[h] = ctx[bs*T_ + h];
        __syncthreads();
        float e = (float)h * (1.0f/255.0f);
        float acc = 0.f;
#pragma unroll
        for (int t = 0; t < T_; t++){
            float s = (float)t * (1.0f/31.0f);
            float l = 1.0f - s - e*(1.0f - 2.0f*s);
            acc += emb[(size_t)ids[t]*H_ + h] * l;
        }
        bf16 hi, lo; split_bf16_(acc, hi, lo);
        bf16* dst = g_ctxA + (size_t)bs*KTOT;
        dst[h] = hi; dst[h + 256] = hi; dst[h + 512] = lo;
    } else if (bid < PREP_QEMB){
        int i = bid - PREP_EMB;
        float v = emb[(size_t)q[i]*H_ + h];
        bf16 hi, lo; split_bf16_(v, hi, lo);
        bf16* dst = g_qA + (size_t)i*KTOT;
        dst[h] = hi; dst[h + 256] = hi; dst[h + 512] = lo;
    } else {
        int idx = bid - PREP_QEMB;
        int sel = idx / G3, n = idx % G3;
        const float* W; bf16* D;
        if (sel == 0){ W = Wf; D = g_wfA; }
        else if (sel == 1){ W = Wb; D = g_wbA; }
        else { W = Wq; D = g_wqA; }
        float v = W[(size_t)n*256 + h];
        bf16 hi, lo; split_bf16_(v, hi, lo);
        bf16* dst = D + (size_t)n*KTOT;
        dst[h] = hi; dst[h + 256] = lo; dst[h + 512] = hi;
    }
}

// ---------------- 2) split-bf16 tensor GEMM for gi (tile 128m x 128n) ----------------
#define AST 72
#define BG3_SMEM_BYTES (2*128*AST*2)
__global__ __launch_bounds__(256) void bgemm3_kernel(
    const float* bias_f, const float* bias_b, const float* bias_q)
{
    extern __shared__ bf16 g3s[];
    bf16* As = g3s;             // [128][72]
    bf16* Bs = g3s + 128*AST;   // [128][72]

    const bf16 *A, *W; const float* bias; float* C; int M;
    if (blockIdx.z == 0){ A = g_ctxA; W = g_wfA; bias = bias_f; C = g_gif; M = B_*S_; }
    else if (blockIdx.z == 1){ A = g_ctxA; W = g_wbA; bias = bias_b; C = g_gib; M = B_*S_; }
    else { A = g_qA; W = g_wqA; bias = bias_q; C = g_giq; M = B_*TQ_; }
    int bm = blockIdx.x * 128;
    if (bm >= M) return;
    int bn = blockIdx.y * 128;

    int tid = threadIdx.x;
    int lane = tid & 31, wid = tid >> 5;
    int wm = (wid & 3) * 32;     // 4 m-groups of 32
    int wn = (wid >> 2) * 64;    // 2 n-groups of 64

    float4 acc[2][8];
#pragma unroll
    for (int i = 0; i < 2; i++)
#pragma unroll
        for (int j = 0; j < 8; j++) acc[i][j] = make_float4(0.f,0.f,0.f,0.f);

    for (int k0 = 0; k0 < KTOT; k0 += 64){
#pragma unroll
        for (int i = 0; i < 4; i++){
            int idx = tid + i*256;
            int r = idx >> 3, ck = idx & 7;
            *(uint4*)(As + r*AST + ck*8) = *(const uint4*)(A + (size_t)(bm + r)*KTOT + k0 + ck*8);
            *(uint4*)(Bs + r*AST + ck*8) = *(const uint4*)(W + (size_t)(bn + r)*KTOT + k0 + ck*8);
        }
        __syncthreads();
        int r = lane >> 2, c2 = (lane & 3) * 2;
#pragma unroll
        for (int kk = 0; kk < 4; kk++){
            unsigned af[2][4], bfr[8][2];
#pragma unroll
            for (int i = 0; i < 2; i++){
                const bf16* ab = As + (wm + i*16)*AST + kk*16;
                af[i][0] = *(const unsigned*)(ab + (r    )*AST + c2    );
                af[i][1] = *(const unsigned*)(ab + (r + 8)*AST + c2    );
                af[i][2] = *(const unsigned*)(ab + (r    )*AST + c2 + 8);
                af[i][3] = *(const unsigned*)(ab + (r + 8)*AST + c2 + 8);
            }
#pragma unroll
            for (int j = 0; j < 8; j++){
                const bf16* bb = Bs + (wn + j*8)*AST + kk*16;
                bfr[j][0] = *(const unsigned*)(bb + r*AST + c2    );
                bfr[j][1] = *(const unsigned*)(bb + r*AST + c2 + 8);
            }
#pragma unroll
            for (int i = 0; i < 2; i++)
#pragma unroll
                for (int j = 0; j < 8; j++)
                    mma_bf16_(acc[i][j], af[i], bfr[j]);
        }
        __syncthreads();
    }
    int r = lane >> 2, c2 = (lane & 3) * 2;
#pragma unroll
    for (int i = 0; i < 2; i++){
        int m0 = bm + wm + i*16 + r;
#pragma unroll
        for (int j = 0; j < 8; j++){
            int n0 = bn + wn + j*8 + c2;
            float4 a = acc[i][j];
            float b0 = bias[n0], b1 = bias[n0+1];
            *(float2*)(C + (size_t)m0*G3 + n0)     = make_float2(a.x + b0, a.y + b1);
            *(float2*)(C + (size_t)(m0+8)*G3 + n0) = make_float2(a.z + b0, a.w + b1);
        }
    }
}

// ---------------- 2b) vocab GEMM: inline fp32 W split ----------------
#define VOC_SMEM_BF16 (2*128*AST + 2*64*AST)
#define VOC_SMEM_BYTES (VOC_SMEM_BF16*2)
__global__ __launch_bounds__(256) void bgemm_vocab_kernel(
    const float* __restrict__ Wo, const float* __restrict__ bo, float* __restrict__ out)
{
    extern __shared__ bf16 vs[];
    bf16* Ah = vs;                 // [128][72]
    bf16* Al = vs + 128*AST;       // [128][72]
    bf16* Bh = vs + 2*128*AST;     // [64][72]
    bf16* Bl = Bh + 64*AST;        // [64][72]
    int tid = threadIdx.x;
    int lane = tid & 31, wid = tid >> 5;
    int wm = (wid & 3) * 32;
    int wn = (wid >> 2) * 32;
    int bn = blockIdx.y * 64;

    float4 acc[2][4];
#pragma unroll
    for (int i = 0; i < 2; i++)
#pragma unroll
        for (int j = 0; j < 4; j++) acc[i][j] = make_float4(0.f,0.f,0.f,0.f);

    for (int k0 = 0; k0 < 256; k0 += 64){
#pragma unroll
        for (int i = 0; i < 4; i++){
            int idx = tid + i*256;
            int r = idx >> 3, ck = idx & 7;
            *(uint4*)(Ah + r*AST + ck*8) = *(const uint4*)(g_afA + (size_t)r*KTOT + k0 + ck*8);
            *(uint4*)(Al + r*AST + ck*8) = *(const uint4*)(g_afA + (size_t)r*KTOT + 512 + k0 + ck*8);
        }
#pragma unroll
        for (int i = 0; i < 4; i++){
            int idx = tid + i*256;
            int r = idx >> 4, ck = idx & 15;
            int n = bn + r;
            float4 v = make_float4(0.f,0.f,0.f,0.f);
            if (n < V_) v = *(const float4*)(Wo + (size_t)n*256 + k0 + ck*4);
            bf16 h0,l0,h1,l1,h2,l2,h3,l3;
            split_bf16_(v.x,h0,l0); split_bf16_(v.y,h1,l1);
            split_bf16_(v.z,h2,l2); split_bf16_(v.w,h3,l3);
            *(uint2*)(Bh + r*AST + ck*4) = make_uint2(pack_bf2_(h0,h1), pack_bf2_(h2,h3));
            *(uint2*)(Bl + r*AST + ck*4) = make_uint2(pack_bf2_(l0,l1), pack_bf2_(l2,l3));
        }
        __syncthreads();
        int r = lane >> 2, c2 = (lane & 3) * 2;
#pragma unroll
        for (int kk = 0; kk < 4; kk++){
            unsigned ah[2][4], al[2][4], bh[4][2], bl[4][2];
#pragma unroll
            for (int i = 0; i < 2; i++){
                const bf16* ab = Ah + (wm + i*16)*AST + kk*16;
                const bf16* al_ = Al + (wm + i*16)*AST + kk*16;
                ah[i][0] = *(const unsigned*)(ab  + (r    )*AST + c2    );
                ah[i][1] = *(const unsigned*)(ab  + (r + 8)*AST + c2    );
                ah[i][2] = *(const unsigned*)(ab  + (r    )*AST + c2 + 8);
                ah[i][3] = *(const unsigned*)(ab  + (r + 8)*AST + c2 + 8);
                al[i][0] = *(const unsigned*)(al_ + (r    )*AST + c2    );
                al[i][1] = *(const unsigned*)(al_ + (r + 8)*AST + c2    );
                al[i][2] = *(const unsigned*)(al_ + (r    )*AST + c2 + 8);
                al[i][3] = *(const unsigned*)(al_ + (r + 8)*AST + c2 + 8);
            }
#pragma unroll
            for (int j = 0; j < 4; j++){
                const bf16* bbh = Bh + (wn + j*8)*AST + kk*16;
                const bf16* bbl = Bl + (wn + j*8)*AST + kk*16;
                bh[j][0] = *(const unsigned*)(bbh + r*AST + c2    );
                bh[j][1] = *(const unsigned*)(bbh + r*AST + c2 + 8);
                bl[j][0] = *(const unsigned*)(bbl + r*AST + c2    );
                bl[j][1] = *(const unsigned*)(bbl + r*AST + c2 + 8);
            }
#pragma unroll
            for (int i = 0; i < 2; i++)
#pragma unroll
                for (int j = 0; j < 4; j++){
                    mma_bf16_(acc[i][j], ah[i], bh[j]);
                    mma_bf16_(acc[i][j], ah[i], bl[j]);
                    mma_bf16_(acc[i][j], al[i], bh[j]);
                }
        }
        __syncthreads();
    }
    int r = lane >> 2, c2 = (lane & 3) * 2;
#pragma unroll
    for (int i = 0; i < 2; i++){
        int m0 = wm + i*16 + r;
#pragma unroll
        for (int j = 0; j < 4; j++){
            int n0 = bn + wn + j*8 + c2;
            if (n0 < V_){
                float4 a = acc[i][j];
                float b0 = bo[n0];
                out[(size_t)m0*V_ + n0]     = a.x + b0;
                out[(size_t)(m0+8)*V_ + n0] = a.z + b0;
                if (n0 + 1 < V_){
                    float b1 = bo[n0+1];
                    out[(size_t)m0*V_ + n0 + 1]     = a.y + b1;
                    out[(size_t)(m0+8)*V_ + n0 + 1] = a.w + b1;
                }
            }
        }
    }
}

// ---------------- 3) GRU on tensor cores (R13/R15-proven sync, byte-identical) ----
#define GRU_WST 264
#define GRU_HST 520
#define GRU_WPLANE (192*GRU_WST)
#define GRU_SMEM_BF16 (2*GRU_WPLANE + 16*GRU_HST)
#define GRU_SMEM_BYTES (GRU_SMEM_BF16*2)

__global__ void __cluster_dims__(4,1,1) __launch_bounds__(256,1)
gru_kernel(const float* __restrict__ Whh_f, const float* __restrict__ Whh_b, const float* __restrict__ Whh_q,
           const float* __restrict__ bhh_f, const float* __restrict__ bhh_b, const float* __restrict__ bhh_q)
{
    extern __shared__ bf16 smb[];
    __shared__ ull gru_mbar;              // static smem mbarrier (never aliased)
    bf16* Whi   = smb;                    // [192][264] (dead after preload)
    bf16* Wlo   = smb + GRU_WPLANE;       // [192][264]
    bf16* hbuf0 = smb + 2*GRU_WPLANE;     // [16][520]: k 0-255 hi, 256-511 lo
    bf16* hbuf1 = smb;                    // aliases Whi region

    int tid  = threadIdx.x;
    int lane = tid & 31, w = tid >> 5;
    unsigned rank = ctarank_();
    int cid   = blockIdx.x >> 2;
    int chain = cid >> 3;
    int b0    = (cid & 7) * 16;

    const float *Whh, *bhh, *gi;
    float* outp;
    int steps;
    if (chain == 0){ Whh = Whh_f; bhh = bhh_f; gi = g_gif; outp = g_outf; steps = S_;  }
    else if (chain == 1){ Whh = Whh_b; bhh = bhh_b; gi = g_gib; outp = g_outb; steps = S_;  }
    else { Whh = Whh_q; bhh = bhh_q; gi = g_giq; outp = g_q;    steps = TQ_; }

    unsigned mbar_addr = smem_u32_(&gru_mbar);
    if (tid == 0) mbar_init_(mbar_addr, 1024u);

    // ---- stage + split Whh slice into smem; zero hbuf0
    {
#pragma unroll 4
        for (int rr = 0; rr < 192; rr++){
            int grow = (rr >> 6)*256 + (int)rank*64 + (rr & 63);
            float v = Whh[(size_t)grow*256 + tid];
            bf16 hi, lo; split_bf16_(v, hi, lo);
            Whi[rr*GRU_WST + tid] = hi;
            Wlo[rr*GRU_WST + tid] = lo;
        }
        unsigned* hz = (unsigned*)hbuf0;
        for (int i = tid; i < 16*GRU_HST/2; i += 256) hz[i] = 0u;
    }
    __syncthreads();

    // ---- fragment geometry
    int r  = lane >> 2;
    int c2 = (lane & 3) * 2;
    int jglob0 = (int)rank*64 + w*8 + c2;

    // ---- preload W fragments to registers: Bf[kt][gate][plane][reg]
    unsigned Bf[16][3][2][2];
#pragma unroll
    for (int kt = 0; kt < 16; kt++){
#pragma unroll
        for (int g = 0; g < 3; g++){
            const bf16* ph = Whi + (g*64 + w*8 + r)*GRU_WST + kt*16 + c2;
            const bf16* pl = Wlo + (g*64 + w*8 + r)*GRU_WST + kt*16 + c2;
            Bf[kt][g][0][0] = *(const unsigned*)(ph);
            Bf[kt][g][0][1] = *(const unsigned*)(ph + 8);
            Bf[kt][g][1][0] = *(const unsigned*)(pl);
            Bf[kt][g][1][1] = *(const unsigned*)(pl + 8);
        }
    }

    unsigned hb0 = smem_u32_(hbuf0), hb1 = smem_u32_(hbuf1);
    unsigned arow = (unsigned)((lane & 15)*GRU_HST*2 + ((lane >> 4) << 3)*2);

    // peer mbarrier addresses (fixed; hoisted)
    unsigned mb0 = mapa_(mbar_addr, 0), mb1 = mapa_(mbar_addr, 1);
    unsigned mb2 = mapa_(mbar_addr, 2), mb3 = mapa_(mbar_addr, 3);

    // DSMEM write-target bases for both buffers (hoisted; wb alternates)
    unsigned pw0[4], pw1[4];
#pragma unroll
    for (int i = 0; i < 4; i++){ pw0[i] = mapa_(hb1, (unsigned)i); pw1[i] = mapa_(hb0, (unsigned)i); }

    int bbA = b0 + r, bbB = b0 + r + 8;
    float hpA0 = 0.f, hpA1 = 0.f, hpB0 = 0.f, hpB1 = 0.f;

    // biases are step-invariant: hoist
    float2 br2 = *(const float2*)(bhh       + jglob0);
    float2 bz2 = *(const float2*)(bhh + 256 + jglob0);
    float2 bn2 = *(const float2*)(bhh + 512 + jglob0);

    // staging + preloads + mbarrier init visible cluster-wide before step 0
    cluster_arrive_();
    cluster_wait_();

    for (int step = 0; step < steps; step++){
        int pos = (chain == 1) ? (S_ - 1 - step) : step;
        unsigned rb = (step & 1) ? hb1 : hb0;
        const unsigned* pw = (step & 1) ? pw1 : pw0;
        unsigned abase = rb + arow;
        bool last = (step == steps - 1);

        float4 accR = make_float4(0.f,0.f,0.f,0.f);
        float4 accZ = make_float4(0.f,0.f,0.f,0.f);
        float4 accN = make_float4(0.f,0.f,0.f,0.f);

        // pass 1: A = h_hi, B = W_hi then W_lo (registers)
#pragma unroll
        for (int kt = 0; kt < 16; kt++){
            unsigned af[4];
            ldsm_x4_(af, abase + kt*32);
            mma_bf16_(accR, af, Bf[kt][0][0]);
            mma_bf16_(accZ, af, Bf[kt][1][0]);
            mma_bf16_(accN, af, Bf[kt][2][0]);
            mma_bf16_(accR, af, Bf[kt][0][1]);
            mma_bf16_(accZ, af, Bf[kt][1][1]);
            mma_bf16_(accN, af, Bf[kt][2][1]);
        }

        // gi loads issue here; latency hidden under pass 2
        float2 grA, gzA, gnA, grB, gzB, gnB;
        {
            const float* pA = gi + ((size_t)bbA*steps + pos)*G3 + jglob0;
            const float* pB = gi + ((size_t)bbB*steps + pos)*G3 + jglob0;
            grA = *(const float2*)(pA); gzA = *(const float2*)(pA+256); gnA = *(const float2*)(pA+512);
            grB = *(const float2*)(pB); gzB = *(const float2*)(pB+256); gnB = *(const float2*)(pB+512);
        }

        // pass 2: A = h_lo (k+512B), B = W_hi
#pragma unroll
        for (int kt = 0; kt < 16; kt++){
            unsigned af[4];
            ldsm_x4_(af, abase + 512 + kt*32);
            mma_bf16_(accR, af, Bf[kt][0][0]);
            mma_bf16_(accZ, af, Bf[kt][1][0]);
            mma_bf16_(accN, af, Bf[kt][2][0]);
        }

        float rA0 = fsig_(grA.x + accR.x + br2.x);
        float zA0 = fsig_(gzA.x + accZ.x + bz2.x);
        float nA0 = ftanh_(gnA.x + rA0*(accN.x + bn2.x));
        float hA0 = (1.f - zA0)*nA0 + zA0*hpA0; hpA0 = hA0;
        float rA1 = fsig_(grA.y + accR.y + br2.y);
        float zA1 = fsig_(gzA.y + accZ.y + bz2.y);
        float nA1 = ftanh_(gnA.y + rA1*(accN.y + bn2.y));
        float hA1 = (1.f - zA1)*nA1 + zA1*hpA1; hpA1 = hA1;
        float rB0 = fsig_(grB.x + accR.z + br2.x);
        float zB0 = fsig_(gzB.x + accZ.z + bz2.x);
        float nB0 = ftanh_(gnB.x + rB0*(accN.z + bn2.x));
        float hB0 = (1.f - zB0)*nB0 + zB0*hpB0; hpB0 = hB0;
        float rB1 = fsig_(grB.y + accR.w + br2.y);
        float zB1 = fsig_(gzB.y + accZ.w + bz2.y);
        float nB1 = ftanh_(gnB.y + rB1*(accN.w + bn2.y));
        float hB1 = (1.f - zB1)*nB1 + zB1*hpB1; hpB1 = hB1;

        if (!last){
            bf16 hiA0, loA0, hiA1, loA1, hiB0, loB0, hiB1, loB1;
            split_bf16_(hA0, hiA0, loA0); split_bf16_(hA1, hiA1, loA1);
            split_bf16_(hB0, hiB0, loB0); split_bf16_(hB1, hiB1, loB1);
            unsigned uAhi = pack_bf2_(hiA0, hiA1), uAlo = pack_bf2_(loA0, loA1);
            unsigned uBhi = pack_bf2_(hiB0, hiB1), uBlo = pack_bf2_(loB0, loB1);

            unsigned offAhi = (unsigned)((r*GRU_HST + jglob0)*2);
            unsigned offAlo = offAhi + 512;
            unsigned offBhi = (unsigned)(((r+8)*GRU_HST + jglob0)*2);
            unsigned offBlo = offBhi + 512;
            st_cluster_u32_(pw[0] + offAhi, uAhi); st_cluster_u32_(pw[0] + offAlo, uAlo);
            st_cluster_u32_(pw[0] + offBhi, uBhi); st_cluster_u32_(pw[0] + offBlo, uBlo);
            st_cluster_u32_(pw[1] + offAhi, uAhi); st_cluster_u32_(pw[1] + offAlo, uAlo);
            st_cluster_u32_(pw[1] + offBhi, uBhi); st_cluster_u32_(pw[1] + offBlo, uBlo);
            st_cluster_u32_(pw[2] + offAhi, uAhi); st_cluster_u32_(pw[2] + offAlo, uAlo);
            st_cluster_u32_(pw[2] + offBhi, uBhi); st_cluster_u32_(pw[2] + offBlo, uBlo);
            st_cluster_u32_(pw[3] + offAhi, uAhi); st_cluster_u32_(pw[3] + offAlo, uAlo);
            st_cluster_u32_(pw[3] + offBhi, uBhi); st_cluster_u32_(pw[3] + offBlo, uBlo);

            // release: per-thread fence orders this thread's DSMEM stores before
            // its own arrivals (overlaps across warps; no CTA rendezvous)
            fence_cluster_();
            mbar_arrive_cluster_(mb0);
            mbar_arrive_cluster_(mb1);
            mbar_arrive_cluster_(mb2);
            mbar_arrive_cluster_(mb3);
        }

        // global outputs overlap the arrive/wait window
        if (chain == 2){
            if (last){
                *(float2*)(outp + (size_t)bbA*H_ + jglob0) = make_float2(hA0, hA1);
                *(float2*)(outp + (size_t)bbB*H_ + jglob0) = make_float2(hB0, hB1);
            }
        } else {
            *(float2*)(outp + ((size_t)bbA*S_ + pos)*H_ + jglob0) = make_float2(hA0, hA1);
            *(float2*)(outp + ((size_t)bbB*S_ + pos)*H_ + jglob0) = make_float2(hB0, hB1);
        }

        if (!last){
            mbar_wait_parity_(mbar_addr, (unsigned)(step & 1));
            fence_cluster_();   // acquire: peer stores visible before next reads
        }
    }
}

// ---------------- 4) attention: 512 threads, smem-cached facts ----------------
#define ATT_SMEM_BYTES (S_*H_*4 + 2*S_*4 + H_*4)
__global__ __launch_bounds__(512) void attn_kernel(){
    extern __shared__ float fs[];          // [S_][H_] cached f = outf+outb
    float* en   = fs + S_*H_;
    float* aw   = en + S_;
    float* red2 = aw + S_;                 // [H_] partial sums from half 1
    int b = blockIdx.x, tid = threadIdx.x;
    int lane = tid & 31, w = tid >> 5;     // 16 warps
    const float* pq = g_q + (size_t)b*H_;

    for (int s = w; s < S_; s += 16){
        const float* pf = g_outf + ((size_t)b*S_ + s)*H_;
        const float* pb = g_outb + ((size_t)b*S_ + s)*H_;
        float p = 0.f;
#pragma unroll
        for (int c = 0; c < 8; c++){
            int hh = c*32 + lane;
            float f = pf[hh] + pb[hh];
            fs[s*H_ + hh] = f;
            p += f * pq[hh];
        }
#pragma unroll
        for (int o = 16; o; o >>= 1) p += __shfl_xor_sync(0xffffffffu, p, o);
        if (lane == 0) en[s] = p;
    }
    __syncthreads();

    if (tid < S_){
        float mx = -1e30f;
        for (int s = 0; s < S_; s++) mx = fmaxf(mx, en[s]);
        float sum = 0.f;
        for (int s = 0; s < S_; s++) sum += fexp_(en[s] - mx);
        aw[tid] = fexp_(en[tid] - mx) * frcp_(sum);
    }
    __syncthreads();

    int h = tid & 255, half = tid >> 8;
    float rd = 0.f;
#pragma unroll 5
    for (int s = half; s < S_; s += 2) rd += aw[s] * fs[s*H_ + h];
    if (half) red2[h] = rd;
    __syncthreads();
    if (!half){
        float v = ftanh_(pq[h] * (rd + red2[h]));
        bf16 hi, lo; split_bf16_(v, hi, lo);
        bf16* dst = g_afA + (size_t)b*KTOT;
        dst[h] = hi; dst[h + 256] = hi; dst[h + 512] = lo;
    }
}

// ---------------- launch ----------------
extern "C" void kernel_launch(void* const* d_in, const int* in_sizes, int n_in,
                              void* d_out, int out_size)
{
    const int*   contexts  = (const int*)  d_in[0];
    const int*   questions = (const int*)  d_in[1];
    const float* emb       = (const float*)d_in[2];
    const float* Wih_f     = (const float*)d_in[3];
    const float* Whh_f     = (const float*)d_in[4];
    const float* bih_f     = (const float*)d_in[5];
    const float* bhh_f     = (const float*)d_in[6];
    const float* Wih_b     = (const float*)d_in[7];
    const float* Whh_b     = (const float*)d_in[8];
    const float* bih_b     = (const float*)d_in[9];
    const float* bhh_b     = (const float*)d_in[10];
    const float* Wih_q     = (const float*)d_in[11];
    const float* Whh_q     = (const float*)d_in[12];
    const float* bih_q     = (const float*)d_in[13];
    const float* bhh_q     = (const float*)d_in[14];
    const float* Wo        = (const float*)d_in[15];
    const float* bo        = (const float*)d_in[16];
    float* out = (float*)d_out;

    cudaFuncSetAttribute(gru_kernel, cudaFuncAttributeMaxDynamicSharedMemorySize, GRU_SMEM_BYTES);
    cudaFuncSetAttribute(bgemm_vocab_kernel, cudaFuncAttributeMaxDynamicSharedMemorySize, VOC_SMEM_BYTES);
    cudaFuncSetAttribute(attn_kernel, cudaFuncAttributeMaxDynamicSharedMemorySize, ATT_SMEM_BYTES);
    cudaFuncSetAttribute(bgemm3_kernel, cudaFuncAttributeMaxDynamicSharedMemorySize, BG3_SMEM_BYTES);

    // 1) fused prep: embeddings + gi weight splits in ONE launch
    prep_kernel<<<PREP_TOTAL, 256>>>(contexts, questions, emb, Wih_f, Wih_b, Wih_q);

    // 2) input-gate GEMMs on tensor cores (128x128 tiles)
    bgemm3_kernel<<<dim3(B_*S_/128, G3/128, 3), 256, BG3_SMEM_BYTES>>>(bih_f, bih_b, bih_q);

    // 3) GRU chains on tensor cores (R13/R15-proven sync)
    gru_kernel<<<96, 256, GRU_SMEM_BYTES>>>(Whh_f, Whh_b, Whh_q, bhh_f, bhh_b, bhh_q);

    // 4) attention + read + tanh (512 threads, smem-cached facts)
    attn_kernel<<<B_, 512, ATT_SMEM_BYTES>>>();

    // 5) vocab projection on tensor cores, inline fp32 W split
    bgemm_vocab_kernel<<<dim3(1, VPAD/64), 256, VOC_SMEM_BYTES>>>(Wo, bo, out);
}